// round 9
// baseline (speedup 1.0000x reference)
#include <cuda_runtime.h>
#include <cuda_fp16.h>
#include <math.h>
#include <stdint.h>

// Problem constants
#define B_  4
#define C_  64
#define HA_ 512
#define WA_ 512
#define N_  256
#define HB_ 32
#define WB_ 32
#define PLANE_ (HA_ * WA_)
#define POS_   (HB_ * WB_)       // 1024
#define THREADS_ 512
#define PPT_ 2                   // positions per thread (2*512 = 1024)
#define NOCT_ 8                  // 8 channel-octs

#define PITCH_ 66                // tile pitch in 16B pixels
#define MAXH_ 46                 // provable bbox height bound
#define TILE_PX_ (MAXH_ * PITCH_)       // 3036 pixels
#define SMEM_BYTES_ (2 * TILE_PX_ * 16) // 97152 B (2 stages)

// Swizzled pixel index: conflict-free LDS.128 for horizontal AND vertical
// lane walks (verified by bank-group enumeration).
__device__ __forceinline__ int swz(int ty, int tx) {
    return ty * PITCH_ + ((ty >> 3) & 3) + (tx ^ (ty & 7));
}

// Reference float chain: grid coord -> pixel coord (monotone)
__device__ __forceinline__ float ref_chain(float g, float sz) {
    float gx = (g + 0.5f) * (2.0f / sz) - 1.0f;
    return ((gx + 1.0f) * sz - 1.0f) * 0.5f;
}

__device__ __forceinline__ unsigned pack_h2(float a, float b) {
    __half2 h = __floats2half2_rn(a, b);
    return *reinterpret_cast<unsigned*>(&h);
}

__global__ __launch_bounds__(THREADS_, 2)
void aerial_patch_sampler_kernel(const float* __restrict__ feat,
                                 const float* __restrict__ pose,
                                 float* __restrict__ out) {
    extern __shared__ uint4 dsm[];          // 2 stages of TILE_PX_ pixels
    uint4* const stage0 = dsm;
    uint4* const stage1 = dsm + TILE_PX_;

    const int n   = blockIdx.x;
    const int b   = blockIdx.y;
    const int tid = threadIdx.x;

    const float* pp = pose + ((size_t)b * N_ + n) * 3;
    const float u_off = pp[0];
    const float v_off = pp[1];
    const float theta = pp[2];
    float s, c;
    sincosf(theta, &s, &c);
    const float cos_r = c;
    const float sin_r = -s;

    // ---- bounding box of the rotated patch ----
    const float a1 = cos_r * 31.0f;
    const float a2 = -sin_r * (-16.0f), a3 = -sin_r * 15.0f;
    const float gu_min = u_off + fminf(0.0f, a1) + fminf(a2, a3);
    const float gu_max = u_off + fmaxf(0.0f, a1) + fmaxf(a2, a3);
    const float b1 = sin_r * 31.0f;
    const float b2 = cos_r * (-16.0f), b3 = cos_r * 15.0f;
    const float gv_min = v_off + fminf(0.0f, b1) + fminf(b2, b3);
    const float gv_max = v_off + fmaxf(0.0f, b1) + fmaxf(b2, b3);

    // Same monotone float chain as the samples -> tile provably covers taps.
    const float ixm = ref_chain(gu_min, (float)WA_);
    const float ixM = ref_chain(gu_max, (float)WA_);
    const float iym = ref_chain(gv_min, (float)HA_);
    const float iyM = ref_chain(gv_max, (float)HA_);

    int x_lo = min(max((int)floorf(ixm), 0), WA_ - 1);
    x_lo = min(x_lo, WA_ - 48);                       // fixed-capacity window
    const int x_hi = min(max((int)floorf(ixM) + 1, 0), WA_ - 1);
    int y_lo = min(max((int)floorf(iym), 0), HA_ - 1);
    y_lo = min(y_lo, HA_ - MAXH_);
    const int y_hi = min(max((int)floorf(iyM) + 1, 0), HA_ - 1);
    const int wmax = max(x_hi - x_lo, 0);             // max tap tx (<= 47)
    const int H = min(max(y_hi - y_lo + 1, 1), MAXH_);
    const int tymax = H - 1;

    // ---- per-thread sample parameters (channel-invariant, pre-swizzled) ----
    int   pk_ab[PPT_];   // lo 16b: o00, hi: o10
    int   pk_cd[PPT_];   // lo 16b: o01, hi: o11
    float w00[PPT_], w10[PPT_], w01[PPT_], w11[PPT_];

    #pragma unroll
    for (int k = 0; k < PPT_; ++k) {
        const int pos = k * THREADS_ + tid;
        const int hb = pos >> 5;
        const int wb = pos & 31;

        const float gu0 = (float)(HB_ - 1 - hb);
        const float gv0 = (float)(wb - WB_ / 2);
        const float gu = u_off + cos_r * gu0 - sin_r * gv0;
        const float gv = v_off + sin_r * gu0 + cos_r * gv0;

        float gx = (gu + 0.5f) * (2.0f / (float)WA_) - 1.0f;
        float gy = (gv + 0.5f) * (2.0f / (float)HA_) - 1.0f;
        const bool valid = (fabsf(gx) < 1.0f) && (fabsf(gy) < 1.0f);
        if (!valid) { gx = 2.0f; gy = 2.0f; }

        const float ix = ((gx + 1.0f) * (float)WA_ - 1.0f) * 0.5f;
        const float iy = ((gy + 1.0f) * (float)HA_ - 1.0f) * 0.5f;

        const float x0f = floorf(ix);
        const float y0f = floorf(iy);
        const float wx1 = ix - x0f;
        const float wx0 = 1.0f - wx1;
        const float wy1 = iy - y0f;
        const float wy0 = 1.0f - wy1;

        const int x0 = (int)x0f, y0 = (int)y0f;
        const int x1 = x0 + 1,   y1 = y0 + 1;

        const bool vx0 = (x0 >= 0) && (x0 < WA_);
        const bool vx1 = (x1 >= 0) && (x1 < WA_);
        const bool vy0 = (y0 >= 0) && (y0 < HA_);
        const bool vy1 = (y1 >= 0) && (y1 < HA_);

        const int tx0 = min(max(min(max(x0, 0), WA_ - 1) - x_lo, 0), wmax);
        const int tx1 = min(max(min(max(x1, 0), WA_ - 1) - x_lo, 0), wmax);
        const int ty0 = min(max(min(max(y0, 0), HA_ - 1) - y_lo, 0), tymax);
        const int ty1 = min(max(min(max(y1, 0), HA_ - 1) - y_lo, 0), tymax);

        pk_ab[k] = swz(ty0, tx0) | (swz(ty0, tx1) << 16);
        pk_cd[k] = swz(ty1, tx0) | (swz(ty1, tx1) << 16);

        w00[k] = (vx0 && vy0) ? (wx0 * wy0) : 0.0f;
        w10[k] = (vx1 && vy0) ? (wx1 * wy0) : 0.0f;
        w01[k] = (vx0 && vy1) ? (wx0 * wy1) : 0.0f;
        w11[k] = (vx1 && vy1) ? (wx1 * wy1) : 0.0f;
    }

    const float* plane0 = feat + (size_t)b * C_ * PLANE_ + (size_t)y_lo * WA_ + x_lo;
    float* outp = out + (((size_t)b * N_ + n) * C_) * (size_t)POS_;

    const int lane = tid & 31;
    const int wrp  = tid >> 5;               // 16 warps; rows wrp, wrp+16, wrp+32

    // ---- loader: 8 channels -> one stage (LDG.32 -> half2 pack -> STS.128)
    auto load_oct = [&](int q, uint4* dst) {
        const float* sq = plane0 + (size_t)(8 * q) * PLANE_;
        #pragma unroll
        for (int i = 0; i < 3; ++i) {
            const int r = wrp + 16 * i;
            if (r < H) {
                const float* row = sq + (size_t)r * WA_;
                const bool doB = (lane + 32 <= wmax);
                float fA[8], fB[8];
                #pragma unroll
                for (int cc = 0; cc < 8; ++cc) {
                    const float* rc = row + (size_t)cc * PLANE_;
                    fA[cc] = __ldg(rc + lane);
                    fB[cc] = doB ? __ldg(rc + lane + 32) : 0.0f;
                }
                uint4 A;
                A.x = pack_h2(fA[0], fA[1]);
                A.y = pack_h2(fA[2], fA[3]);
                A.z = pack_h2(fA[4], fA[5]);
                A.w = pack_h2(fA[6], fA[7]);
                dst[swz(r, lane)] = A;
                if (doB) {
                    uint4 Bv;
                    Bv.x = pack_h2(fB[0], fB[1]);
                    Bv.y = pack_h2(fB[2], fB[3]);
                    Bv.z = pack_h2(fB[4], fB[5]);
                    Bv.w = pack_h2(fB[6], fB[7]);
                    dst[swz(r, lane + 32)] = Bv;
                }
            }
        }
    };

    // prologue
    load_oct(0, stage0);
    __syncthreads();

    for (int q = 0; q < NOCT_; ++q) {
        if (q + 1 < NOCT_)
            load_oct(q + 1, ((q + 1) & 1) ? stage1 : stage0);

        const uint4* tb = (q & 1) ? stage1 : stage0;
        float* oc = outp + (size_t)(8 * q) * POS_;

        #pragma unroll
        for (int k = 0; k < PPT_; ++k) {
            const int o00 = pk_ab[k] & 0xffff;
            const int o10 = (pk_ab[k] >> 16) & 0xffff;
            const int o01 = pk_cd[k] & 0xffff;
            const int o11 = (pk_cd[k] >> 16) & 0xffff;

            const uint4 t00 = tb[o00];
            const uint4 t10 = tb[o10];
            const uint4 t01 = tb[o01];
            const uint4 t11 = tb[o11];

            const unsigned* u00 = reinterpret_cast<const unsigned*>(&t00);
            const unsigned* u10 = reinterpret_cast<const unsigned*>(&t10);
            const unsigned* u01 = reinterpret_cast<const unsigned*>(&t01);
            const unsigned* u11 = reinterpret_cast<const unsigned*>(&t11);

            const int oi = k * THREADS_ + tid;
            #pragma unroll
            for (int j = 0; j < 4; ++j) {
                const float2 p00 = __half22float2(*reinterpret_cast<const __half2*>(&u00[j]));
                const float2 p10 = __half22float2(*reinterpret_cast<const __half2*>(&u10[j]));
                const float2 p01 = __half22float2(*reinterpret_cast<const __half2*>(&u01[j]));
                const float2 p11 = __half22float2(*reinterpret_cast<const __half2*>(&u11[j]));
                const float ra = fmaf(p00.x, w00[k], fmaf(p10.x, w10[k],
                                 fmaf(p01.x, w01[k], p11.x * w11[k])));
                const float rb = fmaf(p00.y, w00[k], fmaf(p10.y, w10[k],
                                 fmaf(p01.y, w01[k], p11.y * w11[k])));
                oc[(size_t)(2 * j) * POS_ + oi]     = ra;
                oc[(size_t)(2 * j + 1) * POS_ + oi] = rb;
            }
        }
        __syncthreads();
    }
}

extern "C" void kernel_launch(void* const* d_in, const int* in_sizes, int n_in,
                              void* d_out, int out_size) {
    const float* aer_feat = (const float*)d_in[0];
    const float* pose_uvr = (const float*)d_in[1];
    float* out = (float*)d_out;

    // Opt in to >48KB dynamic shared memory (idempotent; not a stream op).
    cudaFuncSetAttribute(aerial_patch_sampler_kernel,
                         cudaFuncAttributeMaxDynamicSharedMemorySize, SMEM_BYTES_);

    dim3 grid(N_, B_);
    dim3 block(THREADS_);
    aerial_patch_sampler_kernel<<<grid, block, SMEM_BYTES_>>>(aer_feat, pose_uvr, out);
}